// round 15
// baseline (speedup 1.0000x reference)
#include <cuda_runtime.h>
#include <cuda_fp16.h>
#include <cstdint>

#define NN 100000
#define NE 640000
#define HH 128
#define NU 1000
#define MTILES 782      // ceil(100000/128)
#define SCAN_BLKS 391   // ceil(100000/256)

// ---------------- scratch (static device memory; no runtime allocs) ----------------
__device__ __half g_embh[(size_t)NN * HH];  // emb fp16 (25.6 MB)
__device__ __half g_Z1[(size_t)NN * HH];    // Z1 = A*X  (fp16, 25.6 MB)
__device__ __half g_Z2[(size_t)NN * HH];    // Z2 = A*Z1 (fp16, 25.6 MB)
__device__ float g_deg[NN];
__device__ float g_v[NN];                   // v = A*1
__device__ float g_norm[NE];
__device__ int   g_pos[NE];                 // rank within destination bucket
__device__ int   g_cnt[NN];                 // histogram of destinations
__device__ int   g_off[NN + 1];             // CSR offsets
__device__ unsigned long long g_state[SCAN_BLKS]; // lookback scan state
__device__ unsigned int g_ticket;
__device__ float2 g_sedge[NE];              // sorted (row_bits, norm) by destination
__device__ int   g_is64;

__device__ float g_W2p[128 * NU];           // W2 @ Wp
__device__ float g_Wc[128 * NU];            // W1 @ W2 @ Wp
__device__ float g_c1[NU];                  // b1 @ W2 @ Wp
__device__ float g_c0[NU];                  // b2 @ Wp + bp
__device__ __half g_Wcth[1024 * 128];       // Wc^T fp16 (padded N->1024)

__device__ __forceinline__ int edge_idx(const void* ei, int pos) {
    if (g_is64) return (int)((const long long*)ei)[pos];
    return ((const int*)ei)[pos];
}

// ---------------- zero small arrays + scan state + dtype sniff ----------------
__global__ void zs_kernel(float* deg, float* v, int* cnt, const int* __restrict__ ei32) {
    int i = blockIdx.x * blockDim.x + threadIdx.x;
    if (i == 0) {
        int all_zero = 1;
        for (int k = 0; k < 256; k++) {
            if (ei32[2 * k + 1] != 0) { all_zero = 0; break; }
        }
        g_is64 = all_zero;
        g_ticket = 0u;
    }
    if (i < SCAN_BLKS) g_state[i] = 0ULL;
    if (i < NN) { deg[i] = 0.f; v[i] = 0.f; cnt[i] = 0; }
}

// ---------------- emb -> fp16 ----------------
__global__ void embh_kernel(const float* __restrict__ emb, __half* __restrict__ out) {
    int i = blockIdx.x * blockDim.x + threadIdx.x;
    if (i < NN * HH / 4) {
        float4 v = *reinterpret_cast<const float4*>(emb + (size_t)i * 4);
        __half2 p0 = __halves2half2(__float2half(v.x), __float2half(v.y));
        __half2 p1 = __halves2half2(__float2half(v.z), __float2half(v.w));
        *reinterpret_cast<uint2*>(out + (size_t)i * 4) =
            make_uint2(*(uint32_t*)&p0, *(uint32_t*)&p1);
    }
}

__global__ void deg_kernel(const void* __restrict__ ei, const float* __restrict__ w, float* deg) {
    int e = blockIdx.x * blockDim.x + threadIdx.x;
    if (e < NE) {
        int c = edge_idx(ei, NE + e);
        atomicAdd(deg + c, w[e]);
    }
}

// norm per edge (inline deg^-1/2), v = A*1 accumulation, destination histogram+rank
__global__ void norm_kernel(const void* __restrict__ ei, const float* __restrict__ w,
                            const float* __restrict__ deg, float* __restrict__ nrm,
                            float* __restrict__ v, int* __restrict__ cnt,
                            int* __restrict__ pos) {
    int e = blockIdx.x * blockDim.x + threadIdx.x;
    if (e < NE) {
        int r = edge_idx(ei, e);
        int c = edge_idx(ei, NE + e);
        float dr = __ldg(deg + r), dc = __ldg(deg + c);
        float ir = (dr > 0.f) ? rsqrtf(fmaxf(dr, 1e-30f)) : 0.f;
        float ic = (dc > 0.f) ? rsqrtf(fmaxf(dc, 1e-30f)) : 0.f;
        float val = ir * w[e] * ic;
        nrm[e] = val;
        atomicAdd(v + c, val);
        pos[e] = atomicAdd(cnt + c, 1);
    }
}

// ---------------- single-kernel decoupled-lookback exclusive scan ----------------
__global__ void scan_kernel(const int* __restrict__ cnt, int* __restrict__ off) {
    __shared__ int sm[256];
    __shared__ int s_bid;
    __shared__ int s_prefix;
    int t = threadIdx.x;
    if (t == 0) s_bid = (int)atomicAdd(&g_ticket, 1u);
    __syncthreads();
    const int bid = s_bid;
    const int i = bid * 256 + t;
    int x = (i < NN) ? cnt[i] : 0;
    sm[t] = x;
    __syncthreads();
    #pragma unroll
    for (int d = 1; d < 256; d <<= 1) {
        int y = (t >= d) ? sm[t - d] : 0;
        __syncthreads();
        sm[t] += y;
        __syncthreads();
    }
    const int agg = sm[255];
    if (t == 0) {
        atomicExch(&g_state[bid], (1ULL << 32) | (unsigned)agg);   // partial
        int prefix = 0;
        for (int j = bid - 1; j >= 0; ) {
            unsigned long long s = atomicAdd(&g_state[j], 0ULL);
            unsigned st = (unsigned)(s >> 32);
            if (st == 2u)      { prefix += (int)(unsigned)s; break; }
            else if (st == 1u) { prefix += (int)(unsigned)s; j--; }
            // st==0: spin
        }
        atomicExch(&g_state[bid], (2ULL << 32) | (unsigned)(prefix + agg)); // inclusive
        s_prefix = prefix;
        if (bid == SCAN_BLKS - 1) off[NN] = prefix + agg;
    }
    __syncthreads();
    if (i < NN) off[i] = sm[t] - x + s_prefix;
}

// ---------------- permute edges into CSR order ----------------
__global__ void permute_kernel(const void* __restrict__ ei, const float* __restrict__ nrm,
                               const int* __restrict__ pos, const int* __restrict__ off,
                               float2* __restrict__ sedge) {
    int e = blockIdx.x * blockDim.x + threadIdx.x;
    if (e < NE) {
        int r = edge_idx(ei, e);
        int c = edge_idx(ei, NE + e);
        int dst = off[c] + pos[e];
        sedge[dst] = make_float2(__int_as_float(r), nrm[e]);
    }
}

// ---------------- gather: out[c] = sum nrm * h[row]  (fp16 in, fp16 out) ----------------
__global__ void __launch_bounds__(256)
gather_kernel(const float2* __restrict__ sedge, const int* __restrict__ off,
              const __half* __restrict__ h, __half* __restrict__ out) {
    int wid  = threadIdx.x >> 5;
    int lane = threadIdx.x & 31;
    int c = blockIdx.x * 8 + wid;
    if (c >= NN) return;
    int s = __ldg(off + c), e = __ldg(off + c + 1);
    float4 acc = make_float4(0.f, 0.f, 0.f, 0.f);
    for (int i = s; i < e; i++) {
        float2 ed = __ldg(sedge + i);
        int   r = __float_as_int(ed.x);
        float w = ed.y;
        uint2 hv = *reinterpret_cast<const uint2*>(h + (size_t)r * HH + lane * 4);
        float2 f0 = __half22float2(*reinterpret_cast<__half2*>(&hv.x));
        float2 f1 = __half22float2(*reinterpret_cast<__half2*>(&hv.y));
        acc.x += w * f0.x; acc.y += w * f0.y; acc.z += w * f1.x; acc.w += w * f1.y;
    }
    __half2 p0 = __halves2half2(__float2half(acc.x), __float2half(acc.y));
    __half2 p1 = __halves2half2(__float2half(acc.z), __float2half(acc.w));
    *reinterpret_cast<uint2*>(out + (size_t)c * HH + lane * 4) =
        make_uint2(*(uint32_t*)&p0, *(uint32_t*)&p1);
}

// ---------------- small weight-combine kernels (coalesced: lanes walk n) ----------------
__global__ void smallgemm_kernel(const float* __restrict__ X, const float* __restrict__ Y,
                                 float* __restrict__ C, int N) {
    int i = blockIdx.x * blockDim.x + threadIdx.x;
    if (i >= 128 * N) return;
    int m = i / N, n = i % N;
    float s = 0.f;
    #pragma unroll 8
    for (int k = 0; k < 128; k++) s += X[m * 128 + k] * Y[k * N + n];
    C[i] = s;
}

__global__ void vec_kernel(const float* __restrict__ b1, const float* __restrict__ W2p,
                           const float* __restrict__ b2, const float* __restrict__ Wp,
                           const float* __restrict__ bp,
                           float* __restrict__ c1, float* __restrict__ c0) {
    int n = blockIdx.x * blockDim.x + threadIdx.x;
    if (n >= NU) return;
    float s1 = 0.f, s0 = 0.f;
    #pragma unroll 8
    for (int k = 0; k < 128; k++) {
        s1 += b1[k] * W2p[k * NU + n];
        s0 += b2[k] * Wp[k * NU + n];
    }
    c1[n] = s1;
    c0[n] = s0 + bp[n];
}

__global__ void split_w_kernel(const float* __restrict__ W, __half* __restrict__ bh,
                               int N, int Npad) {
    int i = blockIdx.x * blockDim.x + threadIdx.x;
    if (i < Npad * 128) {
        int n = i >> 7, k = i & 127;
        float v = (n < N) ? W[k * N + n] : 0.f;
        bh[i] = __float2half(v);
    }
}

// =====================================================================================
//  Single-pass fp16 mma.sync GEMM + rank-1 epilogue (R14 structure, unchanged):
//  out[r, n] = (Z2 @ Wc)[r, n] + v[r]*c1[n] + c0[n]
//  CTA tile 128M x 128N; grid (4, 782); 2 N-tiles per CTA; 2 CTAs/SM.
// =====================================================================================

__device__ __forceinline__ uint32_t smem_u32(const void* p) {
    uint32_t a;
    asm("{ .reg .u64 t; cvta.to.shared.u64 t, %1; cvt.u32.u64 %0, t; }" : "=r"(a) : "l"(p));
    return a;
}

#define LDSM4(r0, r1, r2, r3, addr)                                              \
    asm volatile("ldmatrix.sync.aligned.m8n8.x4.shared.b16 {%0,%1,%2,%3}, [%4];" \
                 : "=r"(r0), "=r"(r1), "=r"(r2), "=r"(r3) : "r"(addr))

#define MMA16816(c0, c1, c2, c3, a0, a1, a2, a3, b0, b1)                      \
    asm volatile("mma.sync.aligned.m16n8k16.row.col.f32.f16.f16.f32 "         \
                 "{%0,%1,%2,%3},{%4,%5,%6,%7},{%8,%9},{%0,%1,%2,%3};"         \
                 : "+f"(c0), "+f"(c1), "+f"(c2), "+f"(c3)                     \
                 : "r"(a0), "r"(a1), "r"(a2), "r"(a3), "r"(b0), "r"(b1))

#define S_A    0u           // 128*272 fp16 A tile
#define S_B    34816u       // 128*272 fp16 B tile
#define GEMM_MMA_SMEM 69632

__global__ void __launch_bounds__(256, 2)
gemm_out(const __half* __restrict__ A, const __half* __restrict__ Bh,
         const float* __restrict__ c0v, const float* __restrict__ c1v,
         const float* __restrict__ vrow, float* __restrict__ C) {
    extern __shared__ char smc[];
    const uint32_t sb = smem_u32(smc);

    const int tid  = threadIdx.x;
    const int lane = tid & 31;
    const int wid  = tid >> 5;
    const int wm   = wid & 3;
    const int wn   = wid >> 2;
    const int mt   = blockIdx.y;
    const int m0   = mt * 128;

    // ---- stage A tile once (already fp16): straight 16B copies ----
    #pragma unroll
    for (int it = 0; it < 8; it++) {
        int idx = tid + it * 256;
        int r = idx >> 4, c = idx & 15;
        int row = m0 + r;
        uint4 v = make_uint4(0, 0, 0, 0);
        if (row < NN) v = *reinterpret_cast<const uint4*>(A + (size_t)row * 128 + c * 8);
        *reinterpret_cast<uint4*>(smc + S_A + (uint32_t)r * 272u + (uint32_t)c * 16u) = v;
    }

    const uint32_t lrow = (uint32_t)(lane & 15);
    const uint32_t lkh  = (uint32_t)(lane >> 4) * 16u;
    const uint32_t aoff = ((uint32_t)(wm * 32) + lrow) * 272u + lkh;
    const uint32_t boff = ((uint32_t)(wn * 64) + lrow) * 272u + lkh;

    const int rbase = m0 + wm * 32 + (lane >> 2);
    float vr[4];
    #pragma unroll
    for (int i = 0; i < 4; i++) {
        int rr = rbase + i * 8;
        vr[i] = (rr < NN) ? __ldg(vrow + rr) : 0.f;
    }

    #pragma unroll 1
    for (int q = 0; q < 2; q++) {
        const int nt = blockIdx.x * 2 + q;

        // ---- stage B tile (fp16, 128 n-rows; padded table always in-bounds) ----
        #pragma unroll
        for (int it = 0; it < 8; it++) {
            int idx = tid + it * 256;
            int r = idx >> 4, c = idx & 15;
            int n = nt * 128 + r;
            uint4 vh = *reinterpret_cast<const uint4*>(Bh + (size_t)n * 128 + c * 8);
            uint32_t o = (uint32_t)r * 272u + (uint32_t)c * 16u;
            *reinterpret_cast<uint4*>(smc + S_B + o) = vh;
        }
        __syncthreads();

        float acc[2][8][4];
        #pragma unroll
        for (int i = 0; i < 2; i++)
            #pragma unroll
            for (int j = 0; j < 8; j++)
                #pragma unroll
                for (int p = 0; p < 4; p++) acc[i][j][p] = 0.f;

        {
            const uint32_t abase = sb + S_A + aoff;
            const uint32_t bbase = sb + S_B + boff;
            #pragma unroll
            for (int ks = 0; ks < 8; ks++) {
                const uint32_t ko = (uint32_t)ks * 32u;
                uint32_t a[2][4];
                LDSM4(a[0][0], a[0][1], a[0][2], a[0][3], abase + ko);
                LDSM4(a[1][0], a[1][1], a[1][2], a[1][3], abase + ko + 16u * 272u);
                uint32_t b[4][4];
                #pragma unroll
                for (int jj = 0; jj < 4; jj++)
                    LDSM4(b[jj][0], b[jj][1], b[jj][2], b[jj][3],
                          bbase + ko + (uint32_t)jj * 16u * 272u);
                #pragma unroll
                for (int i = 0; i < 2; i++) {
                    #pragma unroll
                    for (int jj = 0; jj < 4; jj++) {
                        MMA16816(acc[i][jj * 2][0], acc[i][jj * 2][1],
                                 acc[i][jj * 2][2], acc[i][jj * 2][3],
                                 a[i][0], a[i][1], a[i][2], a[i][3], b[jj][0], b[jj][2]);
                        MMA16816(acc[i][jj * 2 + 1][0], acc[i][jj * 2 + 1][1],
                                 acc[i][jj * 2 + 1][2], acc[i][jj * 2 + 1][3],
                                 a[i][0], a[i][1], a[i][2], a[i][3], b[jj][1], b[jj][3]);
                    }
                }
            }
        }

        // ---- epilogue: out = acc + v[r]*c1[col] + c0[col] ----
        const int cbase = nt * 128 + wn * 64 + (lane & 3) * 2;
        #pragma unroll
        for (int i = 0; i < 2; i++) {
            const int r0 = rbase + i * 16;
            const int r1 = r0 + 8;
            const float v0 = vr[i * 2], v1 = vr[i * 2 + 1];
            #pragma unroll
            for (int j = 0; j < 8; j++) {
                const int col = cbase + j * 8;
                if (col >= NU) continue;
                float2 c1f = __ldg(reinterpret_cast<const float2*>(c1v + col));
                float2 c0f = __ldg(reinterpret_cast<const float2*>(c0v + col));
                if (r0 < NN) {
                    float2 o = make_float2(acc[i][j][0] + v0 * c1f.x + c0f.x,
                                           acc[i][j][1] + v0 * c1f.y + c0f.y);
                    *reinterpret_cast<float2*>(C + (size_t)r0 * NU + col) = o;
                }
                if (r1 < NN) {
                    float2 o = make_float2(acc[i][j][2] + v1 * c1f.x + c0f.x,
                                           acc[i][j][3] + v1 * c1f.y + c0f.y);
                    *reinterpret_cast<float2*>(C + (size_t)r1 * NU + col) = o;
                }
            }
        }
        __syncthreads();   // all warps done with B smem before next q overwrites
    }
}

// ---------------- launch ----------------
extern "C" void kernel_launch(void* const* d_in, const int* in_sizes, int n_in,
                              void* d_out, int out_size) {
    const void*  ei  = d_in[0];
    const float* ew  = (const float*)d_in[1];
    const float* emb = (const float*)d_in[2];
    const float* W1  = (const float*)d_in[3];
    const float* b1  = (const float*)d_in[4];
    const float* W2  = (const float*)d_in[5];
    const float* b2  = (const float*)d_in[6];
    const float* Wp  = (const float*)d_in[7];
    const float* bp  = (const float*)d_in[8];
    float* out = (float*)d_out;

    float *deg, *v, *nrm, *w2p, *wc, *c1, *c0;
    int *pos, *cnt, *off;
    float2 *sedge;
    __half *embh, *z1, *z2, *wcth;
    cudaGetSymbolAddress((void**)&embh,  g_embh);
    cudaGetSymbolAddress((void**)&z1,    g_Z1);
    cudaGetSymbolAddress((void**)&z2,    g_Z2);
    cudaGetSymbolAddress((void**)&deg,   g_deg);
    cudaGetSymbolAddress((void**)&v,     g_v);
    cudaGetSymbolAddress((void**)&nrm,   g_norm);
    cudaGetSymbolAddress((void**)&pos,   g_pos);
    cudaGetSymbolAddress((void**)&cnt,   g_cnt);
    cudaGetSymbolAddress((void**)&off,   g_off);
    cudaGetSymbolAddress((void**)&sedge, g_sedge);
    cudaGetSymbolAddress((void**)&w2p,   g_W2p);
    cudaGetSymbolAddress((void**)&wc,    g_Wc);
    cudaGetSymbolAddress((void**)&c1,    g_c1);
    cudaGetSymbolAddress((void**)&c0,    g_c0);
    cudaGetSymbolAddress((void**)&wcth,  g_Wcth);

    cudaFuncSetAttribute(gemm_out, cudaFuncAttributeMaxDynamicSharedMemorySize,
                         GEMM_MMA_SMEM);

    // prep + counting sort to CSR
    zs_kernel<<<(NN + 255) / 256, 256>>>(deg, v, cnt, (const int*)ei);               // 1
    deg_kernel<<<(NE + 255) / 256, 256>>>(ei, ew, deg);                              // 2
    norm_kernel<<<(NE + 255) / 256, 256>>>(ei, ew, deg, nrm, v, cnt, pos);           // 3
    embh_kernel<<<(NN * HH / 4 + 255) / 256, 256>>>(emb, embh);                      // 4
    scan_kernel<<<SCAN_BLKS, 256>>>(cnt, off);                                       // 5
    permute_kernel<<<(NE + 255) / 256, 256>>>(ei, nrm, pos, off, sedge);             // 6

    // two aggregation layers as gather-reduce (atomic-free; fp16 end-to-end)
    gather_kernel<<<(NN + 7) / 8, 256>>>(sedge, off, embh, z1);                      // 7
    gather_kernel<<<(NN + 7) / 8, 256>>>(sedge, off, z1, z2);                        // 8

    // weight combine + fp16 pack (coalesced versions)
    smallgemm_kernel<<<(128 * NU + 255) / 256, 256>>>(W2, Wp, w2p, NU);              // 9
    smallgemm_kernel<<<(128 * NU + 255) / 256, 256>>>(W1, w2p, wc, NU);              // 10
    vec_kernel<<<(NU + 255) / 256, 256>>>(b1, w2p, b2, Wp, bp, c1, c0);              // 11
    split_w_kernel<<<(1024 * 128 + 255) / 256, 256>>>(wc, wcth, NU, 1024);           // 12

    gemm_out<<<dim3(4, MTILES), 256, GEMM_MMA_SMEM>>>(z2, wcth, c0, c1, v, out);     // 13
}

// round 16
// speedup vs baseline: 1.1063x; 1.1063x over previous
#include <cuda_runtime.h>
#include <cuda_fp16.h>
#include <cstdint>

#define NN 100000
#define NE 640000
#define HH 128
#define NU 1000
#define MTILES 782      // ceil(100000/128)
#define SCAN_BLKS 391   // ceil(100000/256)

// ---------------- scratch (static device memory; no runtime allocs) ----------------
__device__ __half g_Z1[(size_t)NN * HH];    // Z1 = A*X  (fp16, 25.6 MB)
__device__ __half g_Z2[(size_t)NN * HH];    // Z2 = A*Z1 (fp16, 25.6 MB)
__device__ float g_deg[NN];
__device__ float g_v[NN];                   // v = A*1
__device__ float g_norm[NE];
__device__ int   g_pos[NE];                 // rank within destination bucket
__device__ int   g_cnt[NN];                 // histogram of destinations
__device__ int   g_off[NN + 1];             // CSR offsets
__device__ int   g_part[512];               // scan partials
__device__ float2 g_sedge[NE];              // sorted (row_bits, norm) by destination
__device__ int   g_is64;

__device__ float g_W2p[128 * NU];           // W2 @ Wp
__device__ float g_Wc[128 * NU];            // W1 @ W2 @ Wp
__device__ float g_c1[NU];                  // b1 @ W2 @ Wp
__device__ float g_c0[NU];                  // b2 @ Wp + bp
__device__ __half g_Wcth[1024 * 128];       // Wc^T fp16 (padded N->1024)

__device__ __forceinline__ int edge_idx(const void* ei, int pos) {
    if (g_is64) return (int)((const long long*)ei)[pos];
    return ((const int*)ei)[pos];
}

// ---------------- zero small arrays + dtype sniff ----------------
__global__ void zs_kernel(float* deg, float* v, int* cnt, const int* __restrict__ ei32) {
    int i = blockIdx.x * blockDim.x + threadIdx.x;
    if (i == 0) {
        int all_zero = 1;
        for (int k = 0; k < 256; k++) {
            if (ei32[2 * k + 1] != 0) { all_zero = 0; break; }
        }
        g_is64 = all_zero;
    }
    if (i < NN) { deg[i] = 0.f; v[i] = 0.f; cnt[i] = 0; }
}

__global__ void deg_kernel(const void* __restrict__ ei, const float* __restrict__ w, float* deg) {
    int e = blockIdx.x * blockDim.x + threadIdx.x;
    if (e < NE) {
        int c = edge_idx(ei, NE + e);
        atomicAdd(deg + c, w[e]);
    }
}

// norm per edge (inline deg^-1/2), v = A*1 accumulation, destination histogram+rank
__global__ void norm_kernel(const void* __restrict__ ei, const float* __restrict__ w,
                            const float* __restrict__ deg, float* __restrict__ nrm,
                            float* __restrict__ v, int* __restrict__ cnt,
                            int* __restrict__ pos) {
    int e = blockIdx.x * blockDim.x + threadIdx.x;
    if (e < NE) {
        int r = edge_idx(ei, e);
        int c = edge_idx(ei, NE + e);
        float dr = __ldg(deg + r), dc = __ldg(deg + c);
        float ir = (dr > 0.f) ? rsqrtf(fmaxf(dr, 1e-30f)) : 0.f;
        float ic = (dc > 0.f) ? rsqrtf(fmaxf(dc, 1e-30f)) : 0.f;
        float val = ir * w[e] * ic;
        nrm[e] = val;
        atomicAdd(v + c, val);
        pos[e] = atomicAdd(cnt + c, 1);
    }
}

// ---------------- 3-phase exclusive scan over cnt[NN] -> off ----------------
__global__ void scan1_kernel(const int* __restrict__ cnt, int* __restrict__ off,
                             int* __restrict__ part) {
    __shared__ int sm[256];
    int t = threadIdx.x;
    int i = blockIdx.x * 256 + t;
    int x = (i < NN) ? cnt[i] : 0;
    sm[t] = x;
    __syncthreads();
    #pragma unroll
    for (int d = 1; d < 256; d <<= 1) {
        int y = (t >= d) ? sm[t - d] : 0;
        __syncthreads();
        sm[t] += y;
        __syncthreads();
    }
    if (i < NN) off[i] = sm[t] - x;
    if (t == 255) part[blockIdx.x] = sm[255];
}

__global__ void scan2_kernel(int* __restrict__ part) {
    __shared__ int sm[512];
    int t = threadIdx.x;
    int x = (t < SCAN_BLKS) ? part[t] : 0;
    sm[t] = x;
    __syncthreads();
    #pragma unroll
    for (int d = 1; d < 512; d <<= 1) {
        int y = (t >= d) ? sm[t - d] : 0;
        __syncthreads();
        sm[t] += y;
        __syncthreads();
    }
    if (t < SCAN_BLKS) part[t] = sm[t] - x;
}

__global__ void scan3_kernel(int* __restrict__ off, const int* __restrict__ part) {
    int i = blockIdx.x * 256 + threadIdx.x;
    if (i < NN) off[i] += part[blockIdx.x];
    if (i == 0) off[NN] = NE;
}

// ---------------- permute edges into CSR order ----------------
__global__ void permute_kernel(const void* __restrict__ ei, const float* __restrict__ nrm,
                               const int* __restrict__ pos, const int* __restrict__ off,
                               float2* __restrict__ sedge) {
    int e = blockIdx.x * blockDim.x + threadIdx.x;
    if (e < NE) {
        int r = edge_idx(ei, e);
        int c = edge_idx(ei, NE + e);
        int dst = off[c] + pos[e];
        sedge[dst] = make_float2(__int_as_float(r), nrm[e]);
    }
}

// ---------------- gather1: Z1[c] = sum nrm * emb[row]  (fp32 in, fp16 out) ----------------
__global__ void __launch_bounds__(256)
gather1_kernel(const float2* __restrict__ sedge, const int* __restrict__ off,
               const float* __restrict__ h, __half* __restrict__ out) {
    int wid  = threadIdx.x >> 5;
    int lane = threadIdx.x & 31;
    int c = blockIdx.x * 8 + wid;
    if (c >= NN) return;
    int s = __ldg(off + c), e = __ldg(off + c + 1);
    float4 acc = make_float4(0.f, 0.f, 0.f, 0.f);
    for (int i = s; i < e; i++) {
        float2 ed = __ldg(sedge + i);
        int   r = __float_as_int(ed.x);
        float w = ed.y;
        float4 hv = *reinterpret_cast<const float4*>(h + (size_t)r * HH + lane * 4);
        acc.x += w * hv.x; acc.y += w * hv.y; acc.z += w * hv.z; acc.w += w * hv.w;
    }
    __half2 p0 = __halves2half2(__float2half(acc.x), __float2half(acc.y));
    __half2 p1 = __halves2half2(__float2half(acc.z), __float2half(acc.w));
    *reinterpret_cast<uint2*>(out + (size_t)c * HH + lane * 4) =
        make_uint2(*(uint32_t*)&p0, *(uint32_t*)&p1);
}

// ---------------- gather2: Z2[c] = sum nrm * Z1[row]  (fp16 in, fp16 out) ----------------
__global__ void __launch_bounds__(256)
gather2_kernel(const float2* __restrict__ sedge, const int* __restrict__ off,
               const __half* __restrict__ h, __half* __restrict__ out) {
    int wid  = threadIdx.x >> 5;
    int lane = threadIdx.x & 31;
    int c = blockIdx.x * 8 + wid;
    if (c >= NN) return;
    int s = __ldg(off + c), e = __ldg(off + c + 1);
    float4 acc = make_float4(0.f, 0.f, 0.f, 0.f);
    for (int i = s; i < e; i++) {
        float2 ed = __ldg(sedge + i);
        int   r = __float_as_int(ed.x);
        float w = ed.y;
        uint2 hv = *reinterpret_cast<const uint2*>(h + (size_t)r * HH + lane * 4);
        float2 f0 = __half22float2(*reinterpret_cast<__half2*>(&hv.x));
        float2 f1 = __half22float2(*reinterpret_cast<__half2*>(&hv.y));
        acc.x += w * f0.x; acc.y += w * f0.y; acc.z += w * f1.x; acc.w += w * f1.y;
    }
    __half2 p0 = __halves2half2(__float2half(acc.x), __float2half(acc.y));
    __half2 p1 = __halves2half2(__float2half(acc.z), __float2half(acc.w));
    *reinterpret_cast<uint2*>(out + (size_t)c * HH + lane * 4) =
        make_uint2(*(uint32_t*)&p0, *(uint32_t*)&p1);
}

// ---------------- small weight-combine kernels (coalesced: lanes walk n) ----------------
__global__ void smallgemm_kernel(const float* __restrict__ X, const float* __restrict__ Y,
                                 float* __restrict__ C, int N) {
    int i = blockIdx.x * blockDim.x + threadIdx.x;
    if (i >= 128 * N) return;
    int m = i / N, n = i % N;
    float s = 0.f;
    #pragma unroll 8
    for (int k = 0; k < 128; k++) s += X[m * 128 + k] * Y[k * N + n];
    C[i] = s;
}

__global__ void vec_kernel(const float* __restrict__ b1, const float* __restrict__ W2p,
                           const float* __restrict__ b2, const float* __restrict__ Wp,
                           const float* __restrict__ bp,
                           float* __restrict__ c1, float* __restrict__ c0) {
    int n = blockIdx.x * blockDim.x + threadIdx.x;
    if (n >= NU) return;
    float s1 = 0.f, s0 = 0.f;
    #pragma unroll 8
    for (int k = 0; k < 128; k++) {
        s1 += b1[k] * W2p[k * NU + n];
        s0 += b2[k] * Wp[k * NU + n];
    }
    c1[n] = s1;
    c0[n] = s0 + bp[n];
}

__global__ void split_w_kernel(const float* __restrict__ W, __half* __restrict__ bh,
                               int N, int Npad) {
    int i = blockIdx.x * blockDim.x + threadIdx.x;
    if (i < Npad * 128) {
        int n = i >> 7, k = i & 127;
        float v = (n < N) ? W[k * N + n] : 0.f;
        bh[i] = __float2half(v);
    }
}

// =====================================================================================
//  Single-pass fp16 mma.sync GEMM + rank-1 epilogue, occupancy 3:
//  out[r, n] = (Z2 @ Wc)[r, n] + v[r]*c1[n] + c0[n]
//  CTA tile 128M x 64N (warp tile 32x32); grid (8, 782); 2 N-tiles per CTA; 3 CTAs/SM.
// =====================================================================================

__device__ __forceinline__ uint32_t smem_u32(const void* p) {
    uint32_t a;
    asm("{ .reg .u64 t; cvta.to.shared.u64 t, %1; cvt.u32.u64 %0, t; }" : "=r"(a) : "l"(p));
    return a;
}

#define LDSM4(r0, r1, r2, r3, addr)                                              \
    asm volatile("ldmatrix.sync.aligned.m8n8.x4.shared.b16 {%0,%1,%2,%3}, [%4];" \
                 : "=r"(r0), "=r"(r1), "=r"(r2), "=r"(r3) : "r"(addr))

#define MMA16816(c0, c1, c2, c3, a0, a1, a2, a3, b0, b1)                      \
    asm volatile("mma.sync.aligned.m16n8k16.row.col.f32.f16.f16.f32 "         \
                 "{%0,%1,%2,%3},{%4,%5,%6,%7},{%8,%9},{%0,%1,%2,%3};"         \
                 : "+f"(c0), "+f"(c1), "+f"(c2), "+f"(c3)                     \
                 : "r"(a0), "r"(a1), "r"(a2), "r"(a3), "r"(b0), "r"(b1))

#define S_A    0u           // 128*272 fp16 A tile
#define S_B    34816u       // 64*272 fp16 B tile
#define GEMM_MMA_SMEM 52224

__global__ void __launch_bounds__(256, 3)
gemm_out(const __half* __restrict__ A, const __half* __restrict__ Bh,
         const float* __restrict__ c0v, const float* __restrict__ c1v,
         const float* __restrict__ vrow, float* __restrict__ C) {
    extern __shared__ char smc[];
    const uint32_t sb = smem_u32(smc);

    const int tid  = threadIdx.x;
    const int lane = tid & 31;
    const int wid  = tid >> 5;
    const int wm   = wid & 3;     // 4 warps over M (32 rows each)
    const int wn   = wid >> 2;    // 2 warps over N (32 cols each)
    const int mt   = blockIdx.y;
    const int m0   = mt * 128;

    // ---- stage A tile once (already fp16): straight 16B copies ----
    #pragma unroll
    for (int it = 0; it < 8; it++) {
        int idx = tid + it * 256;
        int r = idx >> 4, c = idx & 15;
        int row = m0 + r;
        uint4 v = make_uint4(0, 0, 0, 0);
        if (row < NN) v = *reinterpret_cast<const uint4*>(A + (size_t)row * 128 + c * 8);
        *reinterpret_cast<uint4*>(smc + S_A + (uint32_t)r * 272u + (uint32_t)c * 16u) = v;
    }

    const uint32_t lrow = (uint32_t)(lane & 15);
    const uint32_t lkh  = (uint32_t)(lane >> 4) * 16u;
    const uint32_t aoff = ((uint32_t)(wm * 32) + lrow) * 272u + lkh;
    const uint32_t boff = ((uint32_t)(wn * 32) + lrow) * 272u + lkh;

    const int rbase = m0 + wm * 32 + (lane >> 2);
    float vr[4];
    #pragma unroll
    for (int i = 0; i < 4; i++) {
        int rr = rbase + i * 8;
        vr[i] = (rr < NN) ? __ldg(vrow + rr) : 0.f;
    }

    #pragma unroll 1
    for (int q = 0; q < 2; q++) {
        const int nt = blockIdx.x * 2 + q;   // 64-col tile index, 0..15

        // ---- stage B tile (fp16, 64 n-rows; padded table always in-bounds) ----
        #pragma unroll
        for (int it = 0; it < 4; it++) {
            int idx = tid + it * 256;
            int r = idx >> 4, c = idx & 15;
            int n = nt * 64 + r;
            uint4 vh = *reinterpret_cast<const uint4*>(Bh + (size_t)n * 128 + c * 8);
            uint32_t o = (uint32_t)r * 272u + (uint32_t)c * 16u;
            *reinterpret_cast<uint4*>(smc + S_B + o) = vh;
        }
        __syncthreads();

        float acc[2][4][4];
        #pragma unroll
        for (int i = 0; i < 2; i++)
            #pragma unroll
            for (int j = 0; j < 4; j++)
                #pragma unroll
                for (int p = 0; p < 4; p++) acc[i][j][p] = 0.f;

        {
            const uint32_t abase = sb + S_A + aoff;
            const uint32_t bbase = sb + S_B + boff;
            #pragma unroll
            for (int ks = 0; ks < 8; ks++) {
                const uint32_t ko = (uint32_t)ks * 32u;
                uint32_t a[2][4];
                LDSM4(a[0][0], a[0][1], a[0][2], a[0][3], abase + ko);
                LDSM4(a[1][0], a[1][1], a[1][2], a[1][3], abase + ko + 16u * 272u);
                uint32_t b[2][4];
                LDSM4(b[0][0], b[0][1], b[0][2], b[0][3], bbase + ko);
                LDSM4(b[1][0], b[1][1], b[1][2], b[1][3], bbase + ko + 16u * 272u);
                #pragma unroll
                for (int i = 0; i < 2; i++) {
                    #pragma unroll
                    for (int jj = 0; jj < 2; jj++) {
                        MMA16816(acc[i][jj * 2][0], acc[i][jj * 2][1],
                                 acc[i][jj * 2][2], acc[i][jj * 2][3],
                                 a[i][0], a[i][1], a[i][2], a[i][3], b[jj][0], b[jj][2]);
                        MMA16816(acc[i][jj * 2 + 1][0], acc[i][jj * 2 + 1][1],
                                 acc[i][jj * 2 + 1][2], acc[i][jj * 2 + 1][3],
                                 a[i][0], a[i][1], a[i][2], a[i][3], b[jj][1], b[jj][3]);
                    }
                }
            }
        }

        // ---- epilogue: out = acc + v[r]*c1[col] + c0[col] ----
        const int cbase = nt * 64 + wn * 32 + (lane & 3) * 2;
        #pragma unroll
        for (int i = 0; i < 2; i++) {
            const int r0 = rbase + i * 16;
            const int r1 = r0 + 8;
            const float v0 = vr[i * 2], v1 = vr[i * 2 + 1];
            #pragma unroll
            for (int j = 0; j < 4; j++) {
                const int col = cbase + j * 8;
                if (col >= NU) continue;
                float2 c1f = __ldg(reinterpret_cast<const float2*>(c1v + col));
                float2 c0f = __ldg(reinterpret_cast<const float2*>(c0v + col));
                if (r0 < NN) {
                    float2 o = make_float2(acc[i][j][0] + v0 * c1f.x + c0f.x,
                                           acc[i][j][1] + v0 * c1f.y + c0f.y);
                    *reinterpret_cast<float2*>(C + (size_t)r0 * NU + col) = o;
                }
                if (r1 < NN) {
                    float2 o = make_float2(acc[i][j][2] + v1 * c1f.x + c0f.x,
                                           acc[i][j][3] + v1 * c1f.y + c0f.y);
                    *reinterpret_cast<float2*>(C + (size_t)r1 * NU + col) = o;
                }
            }
        }
        __syncthreads();   // all warps done with B smem before next q overwrites
    }
}

// ---------------- launch ----------------
extern "C" void kernel_launch(void* const* d_in, const int* in_sizes, int n_in,
                              void* d_out, int out_size) {
    const void*  ei  = d_in[0];
    const float* ew  = (const float*)d_in[1];
    const float* emb = (const float*)d_in[2];
    const float* W1  = (const float*)d_in[3];
    const float* b1  = (const float*)d_in[4];
    const float* W2  = (const float*)d_in[5];
    const float* b2  = (const float*)d_in[6];
    const float* Wp  = (const float*)d_in[7];
    const float* bp  = (const float*)d_in[8];
    float* out = (float*)d_out;

    float *deg, *v, *nrm, *w2p, *wc, *c1, *c0;
    int *pos, *cnt, *off, *part;
    float2 *sedge;
    __half *z1, *z2, *wcth;
    cudaGetSymbolAddress((void**)&z1,    g_Z1);
    cudaGetSymbolAddress((void**)&z2,    g_Z2);
    cudaGetSymbolAddress((void**)&deg,   g_deg);
    cudaGetSymbolAddress((void**)&v,     g_v);
    cudaGetSymbolAddress((void**)&nrm,   g_norm);
    cudaGetSymbolAddress((void**)&pos,   g_pos);
    cudaGetSymbolAddress((void**)&cnt,   g_cnt);
    cudaGetSymbolAddress((void**)&off,   g_off);
    cudaGetSymbolAddress((void**)&part,  g_part);
    cudaGetSymbolAddress((void**)&sedge, g_sedge);
    cudaGetSymbolAddress((void**)&w2p,   g_W2p);
    cudaGetSymbolAddress((void**)&wc,    g_Wc);
    cudaGetSymbolAddress((void**)&c1,    g_c1);
    cudaGetSymbolAddress((void**)&c0,    g_c0);
    cudaGetSymbolAddress((void**)&wcth,  g_Wcth);

    cudaFuncSetAttribute(gemm_out, cudaFuncAttributeMaxDynamicSharedMemorySize,
                         GEMM_MMA_SMEM);

    // prep + counting sort to CSR (R14 structure)
    zs_kernel<<<(NN + 255) / 256, 256>>>(deg, v, cnt, (const int*)ei);               // 1
    deg_kernel<<<(NE + 255) / 256, 256>>>(ei, ew, deg);                              // 2
    norm_kernel<<<(NE + 255) / 256, 256>>>(ei, ew, deg, nrm, v, cnt, pos);           // 3
    scan1_kernel<<<SCAN_BLKS, 256>>>(cnt, off, part);                                // 4
    scan2_kernel<<<1, 512>>>(part);                                                  // 5
    scan3_kernel<<<SCAN_BLKS, 256>>>(off, part);                                     // 6
    permute_kernel<<<(NE + 255) / 256, 256>>>(ei, nrm, pos, off, sedge);             // 7

    // two aggregation layers as gather-reduce (atomic-free; fp16 intermediates)
    gather1_kernel<<<(NN + 7) / 8, 256>>>(sedge, off, emb, z1);                      // 8
    gather2_kernel<<<(NN + 7) / 8, 256>>>(sedge, off, z1, z2);                       // 9

    // weight combine + fp16 pack (coalesced versions)
    smallgemm_kernel<<<(128 * NU + 255) / 256, 256>>>(W2, Wp, w2p, NU);              // 10
    smallgemm_kernel<<<(128 * NU + 255) / 256, 256>>>(W1, w2p, wc, NU);              // 11
    vec_kernel<<<(NU + 255) / 256, 256>>>(b1, w2p, b2, Wp, bp, c1, c0);              // 12
    split_w_kernel<<<(1024 * 128 + 255) / 256, 256>>>(wc, wcth, NU, 1024);           // 13

    gemm_out<<<dim3(8, MTILES), 256, GEMM_MMA_SMEM>>>(z2, wcth, c0, c1, v, out);     // 14
}